// round 17
// baseline (speedup 1.0000x reference)
#include <cuda_runtime.h>
#include <cuda_fp16.h>

#define N_NODES 50000
#define N_EDGES 800000
#define D_IN    128
#define D_SH    16
#define D_OUT   128
#define N_PATHS 64
#define SCAN_NB ((N_NODES + 255) / 256)   // 196
#define PERS_NB 592                       // persistent grid: ~4 blocks/SM, 1 wave

// ---- static scratch (no allocations allowed) ----
// INVARIANTS at kernel_launch entry (zero-init at load, re-established each run):
//   d_cnt all zero (scan kernel zeroes after read)
//   d_total == 0   (scatter thread 0 resets it)
__device__ int     d_cnt[N_NODES];
__device__ int     d_start[N_NODES];        // segment begin (permuted placement)
__device__ int     d_stop[N_NODES];         // segment end
__device__ int     d_cursor[N_NODES];
__device__ int     d_total;                 // ticket counter for segment placement
__device__ int2    d_edges[N_EDGES];        // CSR payload: {src, e}
__device__ __half2 d_XkH[N_NODES * 32];     // XkH[n,q] = (coeff[2q]*x[n,ki[2q]], coeff[2q+1]*x[n,ki[2q+1]])

// ---- persistent fused histogram + Xk(half2) precompute ----
__global__ void __launch_bounds__(256)
hist_xk_kernel(const int* __restrict__ dst,
               const float* __restrict__ x,
               const float* __restrict__ coeff,
               const int* __restrict__ ki) {
    int tid = blockIdx.x * 256 + threadIdx.x;
    int stride = PERS_NB * 256;
    for (int e = tid; e < N_EDGES; e += stride)
        atomicAdd(&d_cnt[dst[e]], 1);
    for (int i = tid; i < N_NODES * 32; i += stride) {
        int n = i >> 5;
        int q = i & 31;
        int ki0 = __ldg(&ki[2 * q]),     ki1 = __ldg(&ki[2 * q + 1]);
        float c0 = __ldg(&coeff[2 * q]), c1 = __ldg(&coeff[2 * q + 1]);
        float f0 = c0 * __ldg(&x[n * D_IN + ki0]);
        float f1 = c1 * __ldg(&x[n * D_IN + ki1]);
        d_XkH[i] = __floats2half2_rn(f0, f1);
    }
}

// ---- single-pass scan: block-local exclusive scan + atomic ticket offset ----
__global__ void __launch_bounds__(256) scan_kernel() {
    __shared__ int wsum[8];
    __shared__ int blk_off;
    int t = threadIdx.x;
    int lane = t & 31, wid = t >> 5;
    int i = blockIdx.x * 256 + t;

    int v = 0;
    if (i < N_NODES) {
        v = d_cnt[i];
        d_cnt[i] = 0;                        // re-establish invariant
    }
    int s = v;
    #pragma unroll
    for (int off = 1; off < 32; off <<= 1) {
        int u = __shfl_up_sync(0xffffffffu, s, off);
        if (lane >= off) s += u;
    }
    if (lane == 31) wsum[wid] = s;
    __syncthreads();
    if (wid == 0) {
        int ws = (lane < 8) ? wsum[lane] : 0;
        #pragma unroll
        for (int off = 1; off < 8; off <<= 1) {
            int u = __shfl_up_sync(0xffffffffu, ws, off);
            if (lane >= off) ws += u;
        }
        if (lane < 8) wsum[lane] = ws;
    }
    __syncthreads();
    int incl = s + (wid > 0 ? wsum[wid - 1] : 0);
    if (t == 0) blk_off = atomicAdd(&d_total, wsum[7]);
    __syncthreads();

    if (i < N_NODES) {
        int b0 = blk_off + incl - v;
        d_start[i]  = b0;
        d_stop[i]   = b0 + v;
        d_cursor[i] = b0;
    }
}

// ---- persistent scatter ----
__global__ void __launch_bounds__(256)
scatter_kernel(const int* __restrict__ src,
               const int* __restrict__ dst) {
    int tid = blockIdx.x * 256 + threadIdx.x;
    if (tid == 0) d_total = 0;               // reset ticket for next replay
    int stride = PERS_NB * 256;
    for (int e = tid; e < N_EDGES; e += stride) {
        int d = dst[e];
        int pos = atomicAdd(&d_cursor[d], 1);
        d_edges[pos] = make_int2(src[e], e);
    }
}

// Persistent spmm: one warp per node, warps grid-stride over nodes.
// 592 blocks -> single resident wave, no wave transitions; consecutive nodes
// overlap the previous node's tail latency with the next node's loads.
// Inner loop = R13's best: uniform desc LDG.64, coalesced XkH half2 gather
// (L2-resident 6.4MB), two direct per-lane fp32 sh loads within one 64B row.
__global__ void __launch_bounds__(256)
spmm_kernel(const float* __restrict__ sh,
            const int* __restrict__ kj, const int* __restrict__ ko,
            float* __restrict__ out) {
    __shared__ float buf[8][D_OUT];
    int l = threadIdx.x & 31;
    int w = threadIdx.x >> 5;

    int kj0 = __ldg(&kj[2 * l]),  kj1 = __ldg(&kj[2 * l + 1]);
    int ko0 = __ldg(&ko[2 * l]),  ko1 = __ldg(&ko[2 * l + 1]);
    float* bf = buf[w];

    for (int node = blockIdx.x * 8 + w; node < N_NODES; node += PERS_NB * 8) {
        bf[l] = 0.f; bf[l + 32] = 0.f; bf[l + 64] = 0.f; bf[l + 96] = 0.f;
        __syncwarp();

        float acc0 = 0.f, acc1 = 0.f;
        int beg = d_start[node];
        int end = d_stop[node];

        int j = beg;
        for (; j + 3 < end; j += 4) {
            int2 e0 = d_edges[j];
            int2 e1 = d_edges[j + 1];
            int2 e2 = d_edges[j + 2];
            int2 e3 = d_edges[j + 3];
            __half2 h0 = d_XkH[(size_t)e0.x * 32 + l];
            __half2 h1 = d_XkH[(size_t)e1.x * 32 + l];
            __half2 h2 = d_XkH[(size_t)e2.x * 32 + l];
            __half2 h3 = d_XkH[(size_t)e3.x * 32 + l];
            const float* r0 = sh + (size_t)e0.y * D_SH;
            const float* r1 = sh + (size_t)e1.y * D_SH;
            const float* r2 = sh + (size_t)e2.y * D_SH;
            const float* r3 = sh + (size_t)e3.y * D_SH;
            float s00 = __ldg(r0 + kj0), s01 = __ldg(r0 + kj1);
            float s10 = __ldg(r1 + kj0), s11 = __ldg(r1 + kj1);
            float s20 = __ldg(r2 + kj0), s21 = __ldg(r2 + kj1);
            float s30 = __ldg(r3 + kj0), s31 = __ldg(r3 + kj1);
            float2 x0 = __half22float2(h0);
            float2 x1 = __half22float2(h1);
            float2 x2 = __half22float2(h2);
            float2 x3 = __half22float2(h3);
            acc0 = fmaf(s00, x0.x, acc0);
            acc1 = fmaf(s01, x0.y, acc1);
            acc0 = fmaf(s10, x1.x, acc0);
            acc1 = fmaf(s11, x1.y, acc1);
            acc0 = fmaf(s20, x2.x, acc0);
            acc1 = fmaf(s21, x2.y, acc1);
            acc0 = fmaf(s30, x3.x, acc0);
            acc1 = fmaf(s31, x3.y, acc1);
        }
        for (; j < end; j++) {
            int2 e0 = d_edges[j];
            __half2 h0 = d_XkH[(size_t)e0.x * 32 + l];
            const float* r0 = sh + (size_t)e0.y * D_SH;
            float s00 = __ldg(r0 + kj0), s01 = __ldg(r0 + kj1);
            float2 x0 = __half22float2(h0);
            acc0 = fmaf(s00, x0.x, acc0);
            acc1 = fmaf(s01, x0.y, acc1);
        }

        atomicAdd(bf + ko0, acc0);
        atomicAdd(bf + ko1, acc1);
        __syncwarp();

        size_t o = (size_t)node * D_OUT;
        out[o + l]      = bf[l];
        out[o + l + 32] = bf[l + 32];
        out[o + l + 64] = bf[l + 64];
        out[o + l + 96] = bf[l + 96];
        __syncwarp();
    }
}

extern "C" void kernel_launch(void* const* d_in, const int* in_sizes, int n_in,
                              void* d_out, int out_size) {
    const float* x     = (const float*)d_in[0];
    const float* sh    = (const float*)d_in[1];
    const float* coeff = (const float*)d_in[2];
    const int*   src   = (const int*)d_in[3];
    const int*   dst   = (const int*)d_in[4];
    const int*   ki    = (const int*)d_in[5];
    const int*   kj    = (const int*)d_in[6];
    const int*   ko    = (const int*)d_in[7];
    float* out = (float*)d_out;

    hist_xk_kernel<<<PERS_NB, 256>>>(dst, x, coeff, ki);
    scan_kernel<<<SCAN_NB, 256>>>();
    scatter_kernel<<<PERS_NB, 256>>>(src, dst);
    spmm_kernel<<<PERS_NB, 256>>>(sh, kj, ko, out);
}